// round 13
// baseline (speedup 1.0000x reference)
#include <cuda_runtime.h>
#include <cstdint>

// Chamfer distance: B=8, N=M=4096, D=3 — exact pruned NN search (round 13).
// Brute force is pinned at the FFMA-3reg rt=2 wall (~44us floor). Instead:
// sort each point set by x; for each source point expand outward from its
// x-position, pruning with (dx)^2 >= best (exact lower bound on |p-g|^2).
// ~300 candidates/src instead of 4096 -> ~13x fewer pair evals.
//
// d(p,g) = |p|^2 + (|g|^2 - 2 p.g); track bestExcl = min(|g|^2 - 2 p.g),
// dist = max(|p|^2 + bestExcl, 0).  Prune side when dx^2 - |p|^2 >= bestExcl.
// R13 = R12 resubmitted after infra failure; sort threads 512 -> 1024.

constexpr int B     = 8;
constexpr int NPTS  = 4096;
constexpr int PAD   = 8;
constexpr int STN   = NPTS + 2 * PAD;          // padded target array
constexpr int SORT_THREADS   = 1024;
constexpr int SEARCH_THREADS = 256;
constexpr int SEARCH_BLOCKS  = 2 * B * (NPTS / SEARCH_THREADS); // 256
constexpr int SEARCH_SMEM    = STN * 16;       // 65792 B

__device__ float4       g_sorted[2][B][NPTS];  // [arr][batch][i] sorted by x
__device__ float        g_bsum[SEARCH_BLOCKS];
__device__ unsigned int g_cnt;

// ---------------------------------------------------------------- sort ----
__global__ __launch_bounds__(SORT_THREADS) void sort_kernel(
    const float* __restrict__ pred, const float* __restrict__ gt)
{
    __shared__ unsigned long long key[NPTS];   // 32KB
    const int bx  = blockIdx.x;                // 16 blocks: arr*8 + b
    const int arr = bx >> 3, b = bx & 7;
    const float* pts = (arr == 0 ? pred : gt) + (size_t)b * NPTS * 3;
    const int tid = threadIdx.x;

    // sortable key: order-preserving uint map of x, index in low bits
    for (int i = tid; i < NPTS; i += SORT_THREADS) {
        unsigned u = __float_as_uint(pts[3 * i]);
        u = (u & 0x80000000u) ? ~u : (u | 0x80000000u);
        key[i] = ((unsigned long long)u << 32) | (unsigned)i;
    }
    __syncthreads();

    // bitonic sort, ascending (2048 compare-exchanges per stage, 2/thread)
    for (int k = 2; k <= NPTS; k <<= 1) {
        for (int j = k >> 1; j > 0; j >>= 1) {
            #pragma unroll 2
            for (int t = tid; t < NPTS / 2; t += SORT_THREADS) {
                const int i  = ((t & ~(j - 1)) << 1) | (t & (j - 1));
                const int ix = i | j;
                const bool asc = ((i & k) == 0);
                const unsigned long long a = key[i], c = key[ix];
                if ((a > c) == asc) { key[i] = c; key[ix] = a; }
            }
            __syncthreads();
        }
    }

    // gather sorted points, precompute |p|^2
    for (int i = tid; i < NPTS; i += SORT_THREADS) {
        const int idx = (int)(key[i] & 0xFFFFFFFFu);
        const float x = pts[3 * idx + 0];
        const float y = pts[3 * idx + 1];
        const float z = pts[3 * idx + 2];
        g_sorted[arr][b][i] = make_float4(x, y, z, fmaf(x, x, fmaf(y, y, z * z)));
    }
}

// -------------------------------------------------------------- search ----
__global__ __launch_bounds__(SEARCH_THREADS) void search_kernel(
    float* __restrict__ out)
{
    extern __shared__ float4 st[];             // STN float4
    __shared__ float sred[SEARCH_THREADS / 32];
    __shared__ int   s_e;

    const int bx    = blockIdx.x;              // 256 blocks
    const int unit  = bx >> 4;                 // 0..15 : dir*8 + b
    const int chunk = bx & 15;
    const int dir   = unit >> 3, b = unit & 7;
    const int tid   = threadIdx.x;
    const int wid   = tid >> 5, lid = tid & 31;

    // load sorted targets (opposite array) into padded smem
    {
        const float4* tg = g_sorted[1 - dir][b];
        for (int i = tid; i < NPTS; i += SEARCH_THREADS) st[PAD + i] = tg[i];
        if (tid < PAD) {
            st[tid]              = make_float4(-1e20f, 0.f, 0.f, 1e30f);
            st[NPTS + PAD + tid] = make_float4( 1e20f, 0.f, 0.f, 1e30f);
        }
    }
    __syncthreads();

    // this thread's source point (sorted order -> warp locality)
    const float4 P  = g_sorted[dir][b][chunk * SEARCH_THREADS + tid];
    const float  px = P.x, pw = P.w;
    const float  mx = -2.0f * P.x, my = -2.0f * P.y, mz = -2.0f * P.z;

    // lower_bound for px over the real range
    int lo = PAD, hi = PAD + NPTS;
    while (lo < hi) {
        const int mid = (lo + hi) >> 1;
        if (st[mid].x < px) lo = mid + 1; else hi = mid;
    }
    const int pos = lo;

    float best = 3.4e38f;                      // min of (|g|^2 - 2 p.g)

    // expand right
    for (int i = pos; ; i += 4) {
        const float dx = st[i].x - px;
        if (fmaf(dx, dx, -pw) >= best) break;  // dx^2 >= pw + best  -> prune
        #pragma unroll
        for (int q = 0; q < 4; ++q) {
            const float4 G = st[i + q];
            float t = fmaf(mz, G.z, G.w);
            t = fmaf(my, G.y, t);
            t = fmaf(mx, G.x, t);
            best = fminf(best, t);
        }
    }
    // expand left
    for (int i = pos - 1; ; i -= 4) {
        const float dx = px - st[i].x;
        if (fmaf(dx, dx, -pw) >= best) break;
        #pragma unroll
        for (int q = 0; q < 4; ++q) {
            const float4 G = st[i - q];
            float t = fmaf(mz, G.z, G.w);
            t = fmaf(my, G.y, t);
            t = fmaf(mx, G.x, t);
            best = fminf(best, t);
        }
    }

    float sum = fmaxf(pw + best, 0.0f);        // this source's NN distance^2

    // block reduction (fixed order -> deterministic)
    #pragma unroll
    for (int off = 16; off; off >>= 1)
        sum += __shfl_down_sync(0xffffffffu, sum, off);
    if (lid == 0) sred[wid] = sum;
    __syncthreads();
    if (wid == 0) {
        float v = (lid < SEARCH_THREADS / 32) ? sred[lid] : 0.0f;
        #pragma unroll
        for (int off = 4; off; off >>= 1)
            v += __shfl_down_sync(0xffffffffu, v, off);
        if (lid == 0) g_bsum[bx] = v;
    }

    // global election: last block sums the 256 partials
    __threadfence();
    if (tid == 0)
        s_e = (atomicAdd(&g_cnt, 1u) == (unsigned)(SEARCH_BLOCKS - 1));
    __syncthreads();
    if (!s_e) return;
    __threadfence();

    {
        float v = __ldcg(&g_bsum[tid]);        // 256 threads, 256 partials
        #pragma unroll
        for (int off = 16; off; off >>= 1)
            v += __shfl_down_sync(0xffffffffu, v, off);
        if (lid == 0) sred[wid] = v;
        __syncthreads();
        if (wid == 0) {
            float t = (lid < SEARCH_THREADS / 32) ? sred[lid] : 0.0f;
            #pragma unroll
            for (int off = 4; off; off >>= 1)
                t += __shfl_down_sync(0xffffffffu, t, off);
            if (lid == 0) {
                out[0] = t * (1.0f / (float)(B * NPTS));
                g_cnt = 0;                     // reset for next graph replay
            }
        }
    }
}

extern "C" void kernel_launch(void* const* d_in, const int* in_sizes, int n_in,
                              void* d_out, int out_size)
{
    const float* pred = (const float*)d_in[0];
    const float* gt   = (const float*)d_in[1];
    float* out        = (float*)d_out;

    cudaFuncSetAttribute(search_kernel,
                         cudaFuncAttributeMaxDynamicSharedMemorySize,
                         SEARCH_SMEM);

    sort_kernel<<<16, SORT_THREADS>>>(pred, gt);
    search_kernel<<<SEARCH_BLOCKS, SEARCH_THREADS, SEARCH_SMEM>>>(out);
}

// round 14
// speedup vs baseline: 1.1667x; 1.1667x over previous
#include <cuda_runtime.h>
#include <cstdint>

// Chamfer distance: B=8, N=M=4096, D=3 — exact pruned NN search, round 14.
// R14 = R13 with (1) chunked 32-candidate evaluation between prune checks
// (breaks the latency-serial expand loop into pipelined ILP bursts) and
// (2) bank-conflict-free skewed addressing in the bitonic sort.
//
// d(p,g) = |p|^2 + (|g|^2 - 2 p.g); track best = min(|g|^2 - 2 p.g);
// dist = max(|p|^2 + best, 0).  Prune a side when dx^2 - |p|^2 >= best
// (exact: d >= dx^2, dx monotone along sorted x).

constexpr int B     = 8;
constexpr int NPTS  = 4096;
constexpr int PAD   = 32;                      // >= chunk overshoot (31)
constexpr int STN   = NPTS + 2 * PAD;
constexpr int SORT_THREADS   = 1024;
constexpr int SEARCH_THREADS = 256;
constexpr int SEARCH_BLOCKS  = 2 * B * (NPTS / SEARCH_THREADS); // 256
constexpr int SEARCH_SMEM    = STN * 16;       // 66560 B

constexpr int SKEWN = NPTS + NPTS / 16 + NPTS / 256;  // 4368

__device__ float4       g_sorted[2][B][NPTS];  // [arr][batch][i] sorted by x
__device__ float        g_bsum[SEARCH_BLOCKS];
__device__ unsigned int g_cnt;

__device__ __forceinline__ int phys(int i) {   // bank-skewed index
    return i + (i >> 4) + (i >> 8);
}

// ---------------------------------------------------------------- sort ----
__global__ __launch_bounds__(SORT_THREADS) void sort_kernel(
    const float* __restrict__ pred, const float* __restrict__ gt)
{
    __shared__ unsigned long long key[SKEWN];  // ~34.9KB, skew-addressed
    const int bx  = blockIdx.x;                // 16 blocks: arr*8 + b
    const int arr = bx >> 3, b = bx & 7;
    const float* pts = (arr == 0 ? pred : gt) + (size_t)b * NPTS * 3;
    const int tid = threadIdx.x;

    // sortable key: order-preserving uint map of x, index in low bits
    for (int i = tid; i < NPTS; i += SORT_THREADS) {
        unsigned u = __float_as_uint(pts[3 * i]);
        u = (u & 0x80000000u) ? ~u : (u | 0x80000000u);
        key[phys(i)] = ((unsigned long long)u << 32) | (unsigned)i;
    }
    __syncthreads();

    // bitonic sort, ascending; 2048 CEs per stage, 2 per thread
    for (int k = 2; k <= NPTS; k <<= 1) {
        for (int j = k >> 1; j > 0; j >>= 1) {
            #pragma unroll 2
            for (int t = tid; t < NPTS / 2; t += SORT_THREADS) {
                const int i  = ((t & ~(j - 1)) << 1) | (t & (j - 1));
                const int ix = i | j;
                const int pi = phys(i), pix = phys(ix);
                const bool asc = ((i & k) == 0);
                const unsigned long long a = key[pi], c = key[pix];
                if ((a > c) == asc) { key[pi] = c; key[pix] = a; }
            }
            __syncthreads();
        }
    }

    // gather sorted points, precompute |p|^2
    for (int i = tid; i < NPTS; i += SORT_THREADS) {
        const int idx = (int)(key[phys(i)] & 0xFFFFFFFFu);
        const float x = pts[3 * idx + 0];
        const float y = pts[3 * idx + 1];
        const float z = pts[3 * idx + 2];
        g_sorted[arr][b][i] = make_float4(x, y, z, fmaf(x, x, fmaf(y, y, z * z)));
    }
}

// -------------------------------------------------------------- search ----
__global__ __launch_bounds__(SEARCH_THREADS) void search_kernel(
    float* __restrict__ out)
{
    extern __shared__ float4 st[];             // STN float4
    __shared__ float sred[SEARCH_THREADS / 32];
    __shared__ int   s_e;

    const int bx    = blockIdx.x;              // 256 blocks
    const int unit  = bx >> 4;                 // 0..15 : dir*8 + b
    const int chunk = bx & 15;
    const int dir   = unit >> 3, b = unit & 7;
    const int tid   = threadIdx.x;
    const int wid   = tid >> 5, lid = tid & 31;

    // load sorted targets (opposite array) into padded smem
    {
        const float4* tg = g_sorted[1 - dir][b];
        for (int i = tid; i < NPTS; i += SEARCH_THREADS) st[PAD + i] = tg[i];
        for (int i = tid; i < PAD; i += SEARCH_THREADS) {
            st[i]              = make_float4(-1e20f, 0.f, 0.f, 1e30f);
            st[NPTS + PAD + i] = make_float4( 1e20f, 0.f, 0.f, 1e30f);
        }
    }
    __syncthreads();

    // this thread's source point (sorted order -> warp locality)
    const float4 P  = g_sorted[dir][b][chunk * SEARCH_THREADS + tid];
    const float  px = P.x, pw = P.w;
    const float  mx = -2.0f * P.x, my = -2.0f * P.y, mz = -2.0f * P.z;

    // lower_bound for px over the real range
    int lo = PAD, hi = PAD + NPTS;
    while (lo < hi) {
        const int mid = (lo + hi) >> 1;
        if (st[mid].x < px) lo = mid + 1; else hi = mid;
    }
    const int pos = lo;

    // 4 independent min accumulators (8-deep chains instead of 32)
    float b0 = 3.4e38f, b1 = 3.4e38f, b2 = 3.4e38f, b3 = 3.4e38f;

    // seed window: 32 candidates around pos, unconditional, fully pipelined
    #pragma unroll
    for (int g = 0; g < 8; ++g) {
        const int i0 = pos - 16 + g * 4;
        const float4 G0 = st[i0 + 0];
        const float4 G1 = st[i0 + 1];
        const float4 G2 = st[i0 + 2];
        const float4 G3 = st[i0 + 3];
        b0 = fminf(b0, fmaf(mx, G0.x, fmaf(my, G0.y, fmaf(mz, G0.z, G0.w))));
        b1 = fminf(b1, fmaf(mx, G1.x, fmaf(my, G1.y, fmaf(mz, G1.z, G1.w))));
        b2 = fminf(b2, fmaf(mx, G2.x, fmaf(my, G2.y, fmaf(mz, G2.z, G2.w))));
        b3 = fminf(b3, fmaf(mx, G3.x, fmaf(my, G3.y, fmaf(mz, G3.z, G3.w))));
    }
    float best = fminf(fminf(b0, b1), fminf(b2, b3));

    // expand right in 32-candidate chunks (check once per chunk)
    int rp = pos + 16;
    while (true) {
        const float dx = st[rp].x - px;
        if (fmaf(dx, dx, -pw) >= best) break;  // sentinels guarantee exit
        #pragma unroll
        for (int g = 0; g < 8; ++g) {
            const int i0 = rp + g * 4;
            const float4 G0 = st[i0 + 0];
            const float4 G1 = st[i0 + 1];
            const float4 G2 = st[i0 + 2];
            const float4 G3 = st[i0 + 3];
            b0 = fminf(b0, fmaf(mx, G0.x, fmaf(my, G0.y, fmaf(mz, G0.z, G0.w))));
            b1 = fminf(b1, fmaf(mx, G1.x, fmaf(my, G1.y, fmaf(mz, G1.z, G1.w))));
            b2 = fminf(b2, fmaf(mx, G2.x, fmaf(my, G2.y, fmaf(mz, G2.z, G2.w))));
            b3 = fminf(b3, fmaf(mx, G3.x, fmaf(my, G3.y, fmaf(mz, G3.z, G3.w))));
        }
        rp += 32;
        best = fminf(fminf(b0, b1), fminf(b2, b3));
    }

    // expand left in 32-candidate chunks
    int lp = pos - 17;
    while (true) {
        const float dx = px - st[lp].x;
        if (fmaf(dx, dx, -pw) >= best) break;
        #pragma unroll
        for (int g = 0; g < 8; ++g) {
            const int i0 = lp - g * 4;
            const float4 G0 = st[i0 - 0];
            const float4 G1 = st[i0 - 1];
            const float4 G2 = st[i0 - 2];
            const float4 G3 = st[i0 - 3];
            b0 = fminf(b0, fmaf(mx, G0.x, fmaf(my, G0.y, fmaf(mz, G0.z, G0.w))));
            b1 = fminf(b1, fmaf(mx, G1.x, fmaf(my, G1.y, fmaf(mz, G1.z, G1.w))));
            b2 = fminf(b2, fmaf(mx, G2.x, fmaf(my, G2.y, fmaf(mz, G2.z, G2.w))));
            b3 = fminf(b3, fmaf(mx, G3.x, fmaf(my, G3.y, fmaf(mz, G3.z, G3.w))));
        }
        lp -= 32;
        best = fminf(fminf(b0, b1), fminf(b2, b3));
    }

    float sum = fmaxf(pw + best, 0.0f);        // this source's NN distance^2

    // block reduction (fixed order -> deterministic)
    #pragma unroll
    for (int off = 16; off; off >>= 1)
        sum += __shfl_down_sync(0xffffffffu, sum, off);
    if (lid == 0) sred[wid] = sum;
    __syncthreads();
    if (wid == 0) {
        float v = (lid < SEARCH_THREADS / 32) ? sred[lid] : 0.0f;
        #pragma unroll
        for (int off = 4; off; off >>= 1)
            v += __shfl_down_sync(0xffffffffu, v, off);
        if (lid == 0) g_bsum[bx] = v;
    }

    // global election: last block sums the 256 partials
    __threadfence();
    if (tid == 0)
        s_e = (atomicAdd(&g_cnt, 1u) == (unsigned)(SEARCH_BLOCKS - 1));
    __syncthreads();
    if (!s_e) return;
    __threadfence();

    {
        float v = __ldcg(&g_bsum[tid]);        // 256 threads, 256 partials
        #pragma unroll
        for (int off = 16; off; off >>= 1)
            v += __shfl_down_sync(0xffffffffu, v, off);
        if (lid == 0) sred[wid] = v;
        __syncthreads();
        if (wid == 0) {
            float t = (lid < SEARCH_THREADS / 32) ? sred[lid] : 0.0f;
            #pragma unroll
            for (int off = 4; off; off >>= 1)
                t += __shfl_down_sync(0xffffffffu, t, off);
            if (lid == 0) {
                out[0] = t * (1.0f / (float)(B * NPTS));
                g_cnt = 0;                     // reset for next graph replay
            }
        }
    }
}

extern "C" void kernel_launch(void* const* d_in, const int* in_sizes, int n_in,
                              void* d_out, int out_size)
{
    const float* pred = (const float*)d_in[0];
    const float* gt   = (const float*)d_in[1];
    float* out        = (float*)d_out;

    cudaFuncSetAttribute(search_kernel,
                         cudaFuncAttributeMaxDynamicSharedMemorySize,
                         SEARCH_SMEM);

    sort_kernel<<<16, SORT_THREADS>>>(pred, gt);
    search_kernel<<<SEARCH_BLOCKS, SEARCH_THREADS, SEARCH_SMEM>>>(out);
}